// round 14
// baseline (speedup 1.0000x reference)
#include <cuda_runtime.h>
#include <cuda_fp16.h>
#include <cstdint>
#include <math.h>

#define NTOK   16384
#define HD     1024
#define MD     2048
#define NE     16
#define SEGALN 128
#define MAXSLOTS (2*NTOK + NE*SEGALN)   // 34816
#define ROWT     (MAXSLOTS/128)         // 272
#define SSTR   20                       // smem pair-stride (16 pairs + 4 pad; 80B rows)

// ---------------- device scratch ----------------
__device__ int   g_counts[NE];
__device__ int   g_cursor[NE];
__device__ int   g_offsets[NE + 1];
__device__ int   g_slot_token[MAXSLOTS];
__device__ float g_slot_w[MAXSLOTS];
__device__ int   g_top_idx[NTOK * 2];
__device__ float g_top_w[NTOK * 2];
__device__ __half g_Xh [(size_t)NTOK * HD];
__device__ __half g_W1h[(size_t)NE * HD * MD];
__device__ __half g_W2h[(size_t)NE * MD * HD];
__device__ __half g_Hh [(size_t)MAXSLOTS * MD];

// ---------------- helpers ----------------
__device__ __forceinline__ uint32_t smem_u32(const void* p) {
    uint32_t a;
    asm("{ .reg .u64 t; cvta.to.shared.u64 t, %1; cvt.u32.u64 %0, t; }" : "=r"(a) : "l"(p));
    return a;
}
__device__ __forceinline__ uint32_t pack2h(float f0, float f1) {
    __half2 h = __floats2half2_rn(f0, f1);
    return *(uint32_t*)&h;
}
__device__ __forceinline__ void mma_f16(float* c, const uint32_t* a, const uint32_t* b) {
    asm volatile("mma.sync.aligned.m16n8k16.row.col.f32.f16.f16.f32 "
        "{%0,%1,%2,%3},{%4,%5,%6,%7},{%8,%9},{%0,%1,%2,%3};"
        : "+f"(c[0]), "+f"(c[1]), "+f"(c[2]), "+f"(c[3])
        : "r"(a[0]), "r"(a[1]), "r"(a[2]), "r"(a[3]), "r"(b[0]), "r"(b[1]));
}
__device__ __forceinline__ void ldsm4(uint32_t& r0, uint32_t& r1, uint32_t& r2, uint32_t& r3,
                                      uint32_t addr) {
    asm volatile("ldmatrix.sync.aligned.m8n8.x4.shared.b16 {%0,%1,%2,%3}, [%4];"
        : "=r"(r0), "=r"(r1), "=r"(r2), "=r"(r3) : "r"(addr));
}

// ---------------- prep: fp32 -> fp16 elementwise ----------------------------
__global__ __launch_bounds__(256) void f2h_kernel(
    const float* __restrict__ src, __half* __restrict__ dst, int n4)
{
    int i = blockIdx.x * blockDim.x + threadIdx.x;
    if (i >= n4) return;
    float4 v = ((const float4*)src)[i];
    uint2 o;
    o.x = pack2h(v.x, v.y);
    o.y = pack2h(v.z, v.w);
    ((uint2*)dst)[i] = o;
}

// ---------------- routing kernels (verified, unchanged) ---------------------
__global__ void init_kernel() {
    int i = blockIdx.x * blockDim.x + threadIdx.x;
    if (i < MAXSLOTS) g_slot_token[i] = -1;
    if (i < NE) g_counts[i] = 0;
}

__global__ __launch_bounds__(256) void gate_kernel(
    const float* __restrict__ X, const float* __restrict__ Wg,
    const float* __restrict__ bg)
{
    int warp = (blockIdx.x * blockDim.x + threadIdx.x) >> 5;
    int lane = threadIdx.x & 31;
    if (warp >= NTOK) return;
    const float* x = X + (size_t)warp * HD;

    float acc[NE];
    #pragma unroll
    for (int e = 0; e < NE; e++) acc[e] = 0.f;
    for (int h = lane; h < HD; h += 32) {
        float xv = x[h];
        const float* wr = Wg + h * NE;
        #pragma unroll
        for (int e = 0; e < NE; e++) acc[e] += xv * wr[e];
    }
    #pragma unroll
    for (int off = 16; off > 0; off >>= 1)
        #pragma unroll
        for (int e = 0; e < NE; e++)
            acc[e] += __shfl_down_sync(0xffffffffu, acc[e], off);
    if (lane == 0) {
        float lg[NE];
        #pragma unroll
        for (int e = 0; e < NE; e++) lg[e] = acc[e] + bg[e];
        int e0 = 0;
        #pragma unroll
        for (int e = 1; e < NE; e++) if (lg[e] > lg[e0]) e0 = e;
        int e1 = (e0 == 0) ? 1 : 0;
        #pragma unroll
        for (int e = 0; e < NE; e++)
            if (e != e0 && lg[e] > lg[e1]) e1 = e;
        float d = expf(lg[e1] - lg[e0]);
        float w0 = 1.0f / (1.0f + d);
        g_top_idx[2 * warp + 0] = e0;  g_top_w[2 * warp + 0] = w0;
        g_top_idx[2 * warp + 1] = e1;  g_top_w[2 * warp + 1] = 1.0f - w0;
        atomicAdd(&g_counts[e0], 1);
        atomicAdd(&g_counts[e1], 1);
    }
}

__global__ void scan_kernel() {
    int off = 0;
    for (int e = 0; e < NE; e++) {
        g_offsets[e] = off;
        g_cursor[e]  = off;
        off = (off + g_counts[e] + (SEGALN - 1)) & ~(SEGALN - 1);
    }
    g_offsets[NE] = off;
}

__global__ void scatter_kernel() {
    int t = blockIdx.x * blockDim.x + threadIdx.x;
    if (t >= NTOK) return;
    #pragma unroll
    for (int k = 0; k < 2; k++) {
        int e = g_top_idx[2 * t + k];
        int pos = atomicAdd(&g_cursor[e], 1);
        g_slot_token[pos] = t;
        g_slot_w[pos]     = g_top_w[2 * t + k];
    }
}

// ---------------- GEMM: 128x128x32 tile, 512 threads = 16 warps (4m x 4n) ---
// Warp tile 32(M) x 32(N); double-buffered smem.

#define BUFU (128 * SSTR)

// warp compute: one BK=32 chunk, warp tile 32x32, acc[2][4][4]
__device__ __forceinline__ void warp_step(
    uint32_t sAaddr, uint32_t sBaddr,
    int m0, int n0, int lane, float acc[2][4][4])
{
    int l7 = lane & 7;
    int aRow = l7 + ((lane >> 3) & 1) * 8;
    int aKp  = (lane >> 4) * 4;
    int bRow = ((lane >> 4) * 8) + l7;
    int bKp  = ((lane >> 3) & 1) * 4;
    #pragma unroll
    for (int s = 0; s < 2; s++) {
        uint32_t af[2][4], bf[4][2];
        #pragma unroll
        for (int mt = 0; mt < 2; mt++) {
            uint32_t addr = sAaddr + (uint32_t)(((m0 + mt * 16 + aRow) * SSTR) + s * 8 + aKp) * 4u;
            ldsm4(af[mt][0], af[mt][1], af[mt][2], af[mt][3], addr);
        }
        #pragma unroll
        for (int ntp = 0; ntp < 2; ntp++) {
            uint32_t addr = sBaddr + (uint32_t)(((n0 + ntp * 16 + bRow) * SSTR) + s * 8 + bKp) * 4u;
            ldsm4(bf[2 * ntp][0], bf[2 * ntp][1], bf[2 * ntp + 1][0], bf[2 * ntp + 1][1], addr);
        }
        #pragma unroll
        for (int mt = 0; mt < 2; mt++)
            #pragma unroll
            for (int nt = 0; nt < 4; nt++)
                mma_f16(acc[mt][nt], af[mt], bf[nt]);
    }
}

// ---------------- fc1: g_Hh = fp16(relu(gather(Xh) @ W1h + b1)) -------------
__global__ __launch_bounds__(512) void fc1_kernel(
    const float* __restrict__ b1)
{
    __shared__ __align__(16) uint32_t sA[2 * BUFU];
    __shared__ __align__(16) uint32_t sB[2 * BUFU];
    __shared__ int stok[128];

    int tid = threadIdx.x, wid = tid >> 5, lane = tid & 31;
    int gid = lane >> 2, tig = lane & 3;
    int m0 = (wid & 3) * 32, n0 = (wid >> 2) * 32;
    int row0 = blockIdx.y * 128, col0 = blockIdx.x * 128;

    int e = 0;
    while (e < NE - 1 && g_offsets[e + 1] <= row0) e++;
    if (tid < 128) stok[tid] = g_slot_token[row0 + tid];
    __syncthreads();

    uint32_t sAaddr = smem_u32(sA), sBaddr = smem_u32(sB);
    // A loader: row = tid>>2 (0..127), quarter = tid&3 -> 8 halves (1 uint4)
    int arow = tid >> 2, aq = tid & 3;
    int atok = stok[arow];
    const __half* asrc = g_Xh + (size_t)(atok < 0 ? 0 : atok) * HD + aq * 8;
    // B loader: col = tid&127, k8 = tid>>7 (0..3) -> 8 strided halves
    int bn = tid & 127, bk8 = tid >> 7;
    const __half* bsrc = g_W1h + (size_t)e * HD * MD + col0 + bn;
    int aPb = arow * SSTR + aq * 4;
    int bPb = bn * SSTR + bk8 * 4;

    float acc[2][4][4];
    #pragma unroll
    for (int mt = 0; mt < 2; mt++)
        #pragma unroll
        for (int nt = 0; nt < 4; nt++)
            #pragma unroll
            for (int j = 0; j < 4; j++) acc[mt][nt][j] = 0.f;

    uint4 aV;
    uint16_t bV[8];
    const int NI = HD / 32;

    // prologue: chunk 0 -> buf 0
    aV = (atok >= 0) ? *(const uint4*)(asrc) : make_uint4(0, 0, 0, 0);
    #pragma unroll
    for (int j = 0; j < 8; j++)
        bV[j] = *(const uint16_t*)(bsrc + (size_t)(bk8 * 8 + j) * MD);
    *(uint4*)&sA[aPb] = aV;
    #pragma unroll
    for (int p = 0; p < 4; p++)
        sB[bPb + p] = (uint32_t)bV[2 * p] | ((uint32_t)bV[2 * p + 1] << 16);
    __syncthreads();

    for (int it = 0; it < NI; it++) {
        int buf = it & 1, nbuf = buf ^ 1;
        bool more = (it + 1 < NI);
        if (more) {
            int k0 = (it + 1) * 32;
            if (atok >= 0) aV = *(const uint4*)(asrc + k0);
            #pragma unroll
            for (int j = 0; j < 8; j++)
                bV[j] = *(const uint16_t*)(bsrc + (size_t)(k0 + bk8 * 8 + j) * MD);
        }
        warp_step(sAaddr + (uint32_t)buf * BUFU * 4u,
                  sBaddr + (uint32_t)buf * BUFU * 4u, m0, n0, lane, acc);
        if (more) {
            uint32_t* dA = sA + nbuf * BUFU;
            uint32_t* dB = sB + nbuf * BUFU;
            *(uint4*)&dA[aPb] = aV;
            #pragma unroll
            for (int p = 0; p < 4; p++)
                dB[bPb + p] = (uint32_t)bV[2 * p] | ((uint32_t)bV[2 * p + 1] << 16);
        }
        __syncthreads();
    }

    #pragma unroll
    for (int mt = 0; mt < 2; mt++) {
        int r = row0 + m0 + mt * 16 + gid;
        #pragma unroll
        for (int nt = 0; nt < 4; nt++) {
            int col = col0 + n0 + nt * 8 + tig * 2;
            float bb0 = b1[e * MD + col], bb1 = b1[e * MD + col + 1];
            uint32_t lo = pack2h(fmaxf(acc[mt][nt][0] + bb0, 0.f),
                                 fmaxf(acc[mt][nt][1] + bb1, 0.f));
            uint32_t hi = pack2h(fmaxf(acc[mt][nt][2] + bb0, 0.f),
                                 fmaxf(acc[mt][nt][3] + bb1, 0.f));
            *(uint32_t*)&g_Hh[(size_t)r * MD + col]       = lo;
            *(uint32_t*)&g_Hh[(size_t)(r + 8) * MD + col] = hi;
        }
    }
}

// ---------------- fc2: out[tok] += w * (g_Hh @ W2h + b2) --------------------
__global__ __launch_bounds__(512) void fc2_kernel(
    const float* __restrict__ b2, float* __restrict__ out)
{
    __shared__ __align__(16) uint32_t sA[2 * BUFU];
    __shared__ __align__(16) uint32_t sB[2 * BUFU];
    __shared__ int   stok[128];
    __shared__ float sw[128];

    int tid = threadIdx.x, wid = tid >> 5, lane = tid & 31;
    int gid = lane >> 2, tig = lane & 3;
    int m0 = (wid & 3) * 32, n0 = (wid >> 2) * 32;
    int row0 = blockIdx.y * 128, col0 = blockIdx.x * 128;

    int e = 0;
    while (e < NE - 1 && g_offsets[e + 1] <= row0) e++;
    if (tid < 128) {
        stok[tid] = g_slot_token[row0 + tid];
        sw[tid]   = g_slot_w[row0 + tid];
    }
    __syncthreads();

    uint32_t sAaddr = smem_u32(sA), sBaddr = smem_u32(sB);
    int arow = tid >> 2, aq = tid & 3;
    const __half* asrc = g_Hh + (size_t)(row0 + arow) * MD + aq * 8;
    int bn = tid & 127, bk8 = tid >> 7;
    const __half* bsrc = g_W2h + (size_t)e * MD * HD + col0 + bn;
    int aPb = arow * SSTR + aq * 4;
    int bPb = bn * SSTR + bk8 * 4;

    float acc[2][4][4];
    #pragma unroll
    for (int mt = 0; mt < 2; mt++)
        #pragma unroll
        for (int nt = 0; nt < 4; nt++)
            #pragma unroll
            for (int j = 0; j < 4; j++) acc[mt][nt][j] = 0.f;

    uint4 aV;
    uint16_t bV[8];
    const int NI = MD / 32;

    aV = *(const uint4*)(asrc);
    #pragma unroll
    for (int j = 0; j < 8; j++)
        bV[j] = *(const uint16_t*)(bsrc + (size_t)(bk8 * 8 + j) * HD);
    *(uint4*)&sA[aPb] = aV;
    #pragma unroll
    for (int p = 0; p < 4; p++)
        sB[bPb + p] = (uint32_t)bV[2 * p] | ((uint32_t)bV[2 * p + 1] << 16);
    __syncthreads();

    for (int it = 0; it < NI; it++) {
        int buf = it & 1, nbuf = buf ^ 1;
        bool more = (it + 1 < NI);
        if (more) {
            int k0 = (it + 1) * 32;
            aV = *(const uint4*)(asrc + k0);
            #pragma unroll
            for (int j = 0; j < 8; j++)
                bV[j] = *(const uint16_t*)(bsrc + (size_t)(k0 + bk8 * 8 + j) * HD);
        }
        warp_step(sAaddr + (uint32_t)buf * BUFU * 4u,
                  sBaddr + (uint32_t)buf * BUFU * 4u, m0, n0, lane, acc);
        if (more) {
            uint32_t* dA = sA + nbuf * BUFU;
            uint32_t* dB = sB + nbuf * BUFU;
            *(uint4*)&dA[aPb] = aV;
            #pragma unroll
            for (int p = 0; p < 4; p++)
                dB[bPb + p] = (uint32_t)bV[2 * p] | ((uint32_t)bV[2 * p + 1] << 16);
        }
        __syncthreads();
    }

    #pragma unroll
    for (int mt = 0; mt < 2; mt++) {
        int rA = m0 + mt * 16 + gid, rB = rA + 8;
        int tokA = stok[rA], tokB = stok[rB];
        float wA = sw[rA], wB = sw[rB];
        #pragma unroll
        for (int nt = 0; nt < 4; nt++) {
            int col = col0 + n0 + nt * 8 + tig * 2;
            float bb0 = b2[e * HD + col], bb1 = b2[e * HD + col + 1];
            if (tokA >= 0) {
                float* op = out + (size_t)tokA * HD + col;
                atomicAdd(op,     wA * (acc[mt][nt][0] + bb0));
                atomicAdd(op + 1, wA * (acc[mt][nt][1] + bb1));
            }
            if (tokB >= 0) {
                float* op = out + (size_t)tokB * HD + col;
                atomicAdd(op,     wB * (acc[mt][nt][2] + bb0));
                atomicAdd(op + 1, wB * (acc[mt][nt][3] + bb1));
            }
        }
    }
}

// ---------------- launch ----------------------------------------------------
extern "C" void kernel_launch(void* const* d_in, const int* in_sizes, int n_in,
                              void* d_out, int out_size)
{
    const float* X  = (const float*)d_in[0];
    const float* Wg = (const float*)d_in[1];
    const float* bg = (const float*)d_in[2];
    const float* W1 = (const float*)d_in[3];
    const float* b1 = (const float*)d_in[4];
    const float* W2 = (const float*)d_in[5];
    const float* b2 = (const float*)d_in[6];
    float* out = (float*)d_out;

    cudaMemsetAsync(out, 0, sizeof(float) * (size_t)NTOK * HD);

    {
        __half* w1h; cudaGetSymbolAddress((void**)&w1h, g_W1h);
        __half* w2h; cudaGetSymbolAddress((void**)&w2h, g_W2h);
        __half* xh;  cudaGetSymbolAddress((void**)&xh,  g_Xh);
        int nW = (int)((size_t)NE * HD * MD / 4);
        int nX = (int)((size_t)NTOK * HD / 4);
        f2h_kernel<<<(nW + 255) / 256, 256>>>(W1, w1h, nW);
        f2h_kernel<<<(nW + 255) / 256, 256>>>(W2, w2h, nW);
        f2h_kernel<<<(nX + 255) / 256, 256>>>(X,  xh,  nX);
    }

    init_kernel<<<(MAXSLOTS + 255) / 256, 256>>>();
    gate_kernel<<<(NTOK * 32 + 255) / 256, 256>>>(X, Wg, bg);
    scan_kernel<<<1, 1>>>();
    scatter_kernel<<<(NTOK + 255) / 256, 256>>>();

    fc1_kernel<<<dim3(MD / 128, ROWT), 512>>>(b1);
    fc2_kernel<<<dim3(HD / 128, ROWT), 512>>>(b2, out);
}

// round 16
// speedup vs baseline: 1.3004x; 1.3004x over previous
#include <cuda_runtime.h>
#include <cuda_fp16.h>
#include <cstdint>
#include <math.h>

#define NTOK   16384
#define HD     1024
#define MD     2048
#define NE     16
#define SEGALN 128
#define MAXSLOTS (2*NTOK + NE*SEGALN)   // 34816
#define ROWT     (MAXSLOTS/128)         // 272
#define SSTR   20                       // A smem pair-stride (80B rows)
#define BSTRH  136                      // B smem k-row stride in halves (272B)
#define BBUF32 (32 * BSTRH / 2)         // 2176 uint32 per B buffer

// ---------------- device scratch ----------------
__device__ int   g_counts[NE];
__device__ int   g_cursor[NE];
__device__ int   g_offsets[NE + 1];
__device__ int   g_slot_token[MAXSLOTS];
__device__ float g_slot_w[MAXSLOTS];
__device__ int   g_top_idx[NTOK * 2];
__device__ float g_top_w[NTOK * 2];
__device__ __half g_Xh [(size_t)NTOK * HD];
__device__ __half g_W1h[(size_t)NE * HD * MD];
__device__ __half g_W2h[(size_t)NE * MD * HD];
__device__ __half g_Hh [(size_t)MAXSLOTS * MD];

// ---------------- helpers ----------------
__device__ __forceinline__ uint32_t smem_u32(const void* p) {
    uint32_t a;
    asm("{ .reg .u64 t; cvta.to.shared.u64 t, %1; cvt.u32.u64 %0, t; }" : "=r"(a) : "l"(p));
    return a;
}
__device__ __forceinline__ uint32_t pack2h(float f0, float f1) {
    __half2 h = __floats2half2_rn(f0, f1);
    return *(uint32_t*)&h;
}
__device__ __forceinline__ void mma_f16(float* c, const uint32_t* a, const uint32_t* b) {
    asm volatile("mma.sync.aligned.m16n8k16.row.col.f32.f16.f16.f32 "
        "{%0,%1,%2,%3},{%4,%5,%6,%7},{%8,%9},{%0,%1,%2,%3};"
        : "+f"(c[0]), "+f"(c[1]), "+f"(c[2]), "+f"(c[3])
        : "r"(a[0]), "r"(a[1]), "r"(a[2]), "r"(a[3]), "r"(b[0]), "r"(b[1]));
}
__device__ __forceinline__ void ldsm4(uint32_t& r0, uint32_t& r1, uint32_t& r2, uint32_t& r3,
                                      uint32_t addr) {
    asm volatile("ldmatrix.sync.aligned.m8n8.x4.shared.b16 {%0,%1,%2,%3}, [%4];"
        : "=r"(r0), "=r"(r1), "=r"(r2), "=r"(r3) : "r"(addr));
}
__device__ __forceinline__ void ldsm4t(uint32_t& r0, uint32_t& r1, uint32_t& r2, uint32_t& r3,
                                       uint32_t addr) {
    asm volatile("ldmatrix.sync.aligned.m8n8.x4.trans.shared.b16 {%0,%1,%2,%3}, [%4];"
        : "=r"(r0), "=r"(r1), "=r"(r2), "=r"(r3) : "r"(addr));
}

// ---------------- prep: fp32 -> fp16 elementwise ----------------------------
__global__ __launch_bounds__(256) void f2h_kernel(
    const float* __restrict__ src, __half* __restrict__ dst, int n4)
{
    int i = blockIdx.x * blockDim.x + threadIdx.x;
    if (i >= n4) return;
    float4 v = ((const float4*)src)[i];
    uint2 o;
    o.x = pack2h(v.x, v.y);
    o.y = pack2h(v.z, v.w);
    ((uint2*)dst)[i] = o;
}

// ---------------- routing kernels (verified, unchanged) ---------------------
__global__ void init_kernel() {
    int i = blockIdx.x * blockDim.x + threadIdx.x;
    if (i < MAXSLOTS) g_slot_token[i] = -1;
    if (i < NE) g_counts[i] = 0;
}

__global__ __launch_bounds__(256) void gate_kernel(
    const float* __restrict__ X, const float* __restrict__ Wg,
    const float* __restrict__ bg)
{
    int warp = (blockIdx.x * blockDim.x + threadIdx.x) >> 5;
    int lane = threadIdx.x & 31;
    if (warp >= NTOK) return;
    const float* x = X + (size_t)warp * HD;

    float acc[NE];
    #pragma unroll
    for (int e = 0; e < NE; e++) acc[e] = 0.f;
    for (int h = lane; h < HD; h += 32) {
        float xv = x[h];
        const float* wr = Wg + h * NE;
        #pragma unroll
        for (int e = 0; e < NE; e++) acc[e] += xv * wr[e];
    }
    #pragma unroll
    for (int off = 16; off > 0; off >>= 1)
        #pragma unroll
        for (int e = 0; e < NE; e++)
            acc[e] += __shfl_down_sync(0xffffffffu, acc[e], off);
    if (lane == 0) {
        float lg[NE];
        #pragma unroll
        for (int e = 0; e < NE; e++) lg[e] = acc[e] + bg[e];
        int e0 = 0;
        #pragma unroll
        for (int e = 1; e < NE; e++) if (lg[e] > lg[e0]) e0 = e;
        int e1 = (e0 == 0) ? 1 : 0;
        #pragma unroll
        for (int e = 0; e < NE; e++)
            if (e != e0 && lg[e] > lg[e1]) e1 = e;
        float d = expf(lg[e1] - lg[e0]);
        float w0 = 1.0f / (1.0f + d);
        g_top_idx[2 * warp + 0] = e0;  g_top_w[2 * warp + 0] = w0;
        g_top_idx[2 * warp + 1] = e1;  g_top_w[2 * warp + 1] = 1.0f - w0;
        atomicAdd(&g_counts[e0], 1);
        atomicAdd(&g_counts[e1], 1);
    }
}

__global__ void scan_kernel() {
    int off = 0;
    for (int e = 0; e < NE; e++) {
        g_offsets[e] = off;
        g_cursor[e]  = off;
        off = (off + g_counts[e] + (SEGALN - 1)) & ~(SEGALN - 1);
    }
    g_offsets[NE] = off;
}

__global__ void scatter_kernel() {
    int t = blockIdx.x * blockDim.x + threadIdx.x;
    if (t >= NTOK) return;
    #pragma unroll
    for (int k = 0; k < 2; k++) {
        int e = g_top_idx[2 * t + k];
        int pos = atomicAdd(&g_cursor[e], 1);
        g_slot_token[pos] = t;
        g_slot_w[pos]     = g_top_w[2 * t + k];
    }
}

// ---------------- GEMM: 128x128x32 tile, 256 threads = 8 warps (2m x 4n) ----
// A smem n-major pairs (as before); B smem k-major [32][128+pad] halves,
// fragments via ldmatrix.x4.trans. Double-buffered.

#define ABUF (128 * SSTR)

// warp compute: one BK=32 chunk, warp tile 64(M) x 32(N), acc[4][4][4]
__device__ __forceinline__ void warp_step(
    uint32_t sAaddr, uint32_t sBaddr,
    int m0, int n0, int lane, float acc[4][4][4])
{
    int l7 = lane & 7;
    int aRow = l7 + ((lane >> 3) & 1) * 8;
    int aKp  = (lane >> 4) * 4;
    int bm = lane >> 3;                 // ldmatrix matrix id 0..3
    int bK = (bm & 1) * 8 + l7;         // k-row within k16 slice
    int bN = (bm >> 1) * 8;             // n offset within n16 pair
    #pragma unroll
    for (int s = 0; s < 2; s++) {
        uint32_t af[4][4], bf[4][2];
        #pragma unroll
        for (int mt = 0; mt < 4; mt++) {
            uint32_t addr = sAaddr + (uint32_t)(((m0 + mt * 16 + aRow) * SSTR) + s * 8 + aKp) * 4u;
            ldsm4(af[mt][0], af[mt][1], af[mt][2], af[mt][3], addr);
        }
        #pragma unroll
        for (int ntp = 0; ntp < 2; ntp++) {
            uint32_t addr = sBaddr +
                (uint32_t)((s * 16 + bK) * BSTRH + n0 + ntp * 16 + bN) * 2u;
            ldsm4t(bf[2 * ntp][0], bf[2 * ntp][1], bf[2 * ntp + 1][0], bf[2 * ntp + 1][1], addr);
        }
        #pragma unroll
        for (int mt = 0; mt < 4; mt++)
            #pragma unroll
            for (int nt = 0; nt < 4; nt++)
                mma_f16(acc[mt][nt], af[mt], bf[nt]);
    }
}

// ---------------- fc1: g_Hh = fp16(relu(gather(Xh) @ W1h + b1)) -------------
__global__ __launch_bounds__(256) void fc1_kernel(
    const float* __restrict__ b1)
{
    __shared__ __align__(16) uint32_t sA[2 * ABUF];
    __shared__ __align__(16) uint32_t sB[2 * BBUF32];
    __shared__ int stok[128];

    int tid = threadIdx.x, wid = tid >> 5, lane = tid & 31;
    int gid = lane >> 2, tig = lane & 3;
    int m0 = (wid >> 2) * 64, n0 = (wid & 3) * 32;
    int row0 = blockIdx.y * 128, col0 = blockIdx.x * 128;

    int e = 0;
    while (e < NE - 1 && g_offsets[e + 1] <= row0) e++;
    if (tid < 128) stok[tid] = g_slot_token[row0 + tid];
    __syncthreads();

    uint32_t sAaddr = smem_u32(sA), sBaddr = smem_u32(sB);
    // A loader: row = tid>>1, half = tid&1 -> 16 halves (2 uint4)
    int arow = tid >> 1, ahalf = tid & 1;
    int atok = stok[arow];
    const __half* asrc = g_Xh + (size_t)(atok < 0 ? 0 : atok) * HD + ahalf * 16;
    int aPb = arow * SSTR + ahalf * 8;
    // B loader (k-major): slot tid -> krow=tid>>4, nq=tid&15; second slot krow+16
    int bkr = tid >> 4, bnq = tid & 15;
    const __half* bsrc = g_W1h + (size_t)e * HD * MD + col0 + bnq * 8;
    int bIdx0 = bkr * (BSTRH / 2) + bnq * 4;
    int bIdx1 = (bkr + 16) * (BSTRH / 2) + bnq * 4;

    float acc[4][4][4];
    #pragma unroll
    for (int mt = 0; mt < 4; mt++)
        #pragma unroll
        for (int nt = 0; nt < 4; nt++)
            #pragma unroll
            for (int j = 0; j < 4; j++) acc[mt][nt][j] = 0.f;

    uint4 aV0, aV1, bU0, bU1;
    const int NI = HD / 32;

    // prologue: chunk 0 -> buf 0
    if (atok >= 0) {
        aV0 = *(const uint4*)(asrc);
        aV1 = *(const uint4*)(asrc + 8);
    } else {
        aV0 = make_uint4(0, 0, 0, 0); aV1 = aV0;
    }
    bU0 = *(const uint4*)(bsrc + (size_t)bkr * MD);
    bU1 = *(const uint4*)(bsrc + (size_t)(bkr + 16) * MD);
    *(uint4*)&sA[aPb]     = aV0;
    *(uint4*)&sA[aPb + 4] = aV1;
    *(uint4*)&sB[bIdx0] = bU0;
    *(uint4*)&sB[bIdx1] = bU1;
    __syncthreads();

    for (int it = 0; it < NI; it++) {
        int buf = it & 1, nbuf = buf ^ 1;
        bool more = (it + 1 < NI);
        if (more) {
            int k0 = (it + 1) * 32;
            if (atok >= 0) {
                aV0 = *(const uint4*)(asrc + k0);
                aV1 = *(const uint4*)(asrc + k0 + 8);
            }
            bU0 = *(const uint4*)(bsrc + (size_t)(k0 + bkr) * MD);
            bU1 = *(const uint4*)(bsrc + (size_t)(k0 + bkr + 16) * MD);
        }
        warp_step(sAaddr + (uint32_t)buf * ABUF * 4u,
                  sBaddr + (uint32_t)buf * BBUF32 * 4u, m0, n0, lane, acc);
        if (more) {
            uint32_t* dA = sA + nbuf * ABUF;
            uint32_t* dB = sB + nbuf * BBUF32;
            *(uint4*)&dA[aPb]     = aV0;
            *(uint4*)&dA[aPb + 4] = aV1;
            *(uint4*)&dB[bIdx0] = bU0;
            *(uint4*)&dB[bIdx1] = bU1;
        }
        __syncthreads();
    }

    #pragma unroll
    for (int mt = 0; mt < 4; mt++) {
        int r = row0 + m0 + mt * 16 + gid;
        #pragma unroll
        for (int nt = 0; nt < 4; nt++) {
            int col = col0 + n0 + nt * 8 + tig * 2;
            float bb0 = b1[e * MD + col], bb1 = b1[e * MD + col + 1];
            uint32_t lo = pack2h(fmaxf(acc[mt][nt][0] + bb0, 0.f),
                                 fmaxf(acc[mt][nt][1] + bb1, 0.f));
            uint32_t hi = pack2h(fmaxf(acc[mt][nt][2] + bb0, 0.f),
                                 fmaxf(acc[mt][nt][3] + bb1, 0.f));
            *(uint32_t*)&g_Hh[(size_t)r * MD + col]       = lo;
            *(uint32_t*)&g_Hh[(size_t)(r + 8) * MD + col] = hi;
        }
    }
}

// ---------------- fc2: out[tok] += w * (g_Hh @ W2h + b2) --------------------
__global__ __launch_bounds__(256) void fc2_kernel(
    const float* __restrict__ b2, float* __restrict__ out)
{
    __shared__ __align__(16) uint32_t sA[2 * ABUF];
    __shared__ __align__(16) uint32_t sB[2 * BBUF32];
    __shared__ int   stok[128];
    __shared__ float sw[128];

    int tid = threadIdx.x, wid = tid >> 5, lane = tid & 31;
    int gid = lane >> 2, tig = lane & 3;
    int m0 = (wid >> 2) * 64, n0 = (wid & 3) * 32;
    int row0 = blockIdx.y * 128, col0 = blockIdx.x * 128;

    int e = 0;
    while (e < NE - 1 && g_offsets[e + 1] <= row0) e++;
    if (tid < 128) {
        stok[tid] = g_slot_token[row0 + tid];
        sw[tid]   = g_slot_w[row0 + tid];
    }
    __syncthreads();

    uint32_t sAaddr = smem_u32(sA), sBaddr = smem_u32(sB);
    int arow = tid >> 1, ahalf = tid & 1;
    const __half* asrc = g_Hh + (size_t)(row0 + arow) * MD + ahalf * 16;
    int aPb = arow * SSTR + ahalf * 8;
    int bkr = tid >> 4, bnq = tid & 15;
    const __half* bsrc = g_W2h + (size_t)e * MD * HD + col0 + bnq * 8;
    int bIdx0 = bkr * (BSTRH / 2) + bnq * 4;
    int bIdx1 = (bkr + 16) * (BSTRH / 2) + bnq * 4;

    float acc[4][4][4];
    #pragma unroll
    for (int mt = 0; mt < 4; mt++)
        #pragma unroll
        for (int nt = 0; nt < 4; nt++)
            #pragma unroll
            for (int j = 0; j < 4; j++) acc[mt][nt][j] = 0.f;

    uint4 aV0, aV1, bU0, bU1;
    const int NI = MD / 32;

    aV0 = *(const uint4*)(asrc);
    aV1 = *(const uint4*)(asrc + 8);
    bU0 = *(const uint4*)(bsrc + (size_t)bkr * HD);
    bU1 = *(const uint4*)(bsrc + (size_t)(bkr + 16) * HD);
    *(uint4*)&sA[aPb]     = aV0;
    *(uint4*)&sA[aPb + 4] = aV1;
    *(uint4*)&sB[bIdx0] = bU0;
    *(uint4*)&sB[bIdx1] = bU1;
    __syncthreads();

    for (int it = 0; it < NI; it++) {
        int buf = it & 1, nbuf = buf ^ 1;
        bool more = (it + 1 < NI);
        if (more) {
            int k0 = (it + 1) * 32;
            aV0 = *(const uint4*)(asrc + k0);
            aV1 = *(const uint4*)(asrc + k0 + 8);
            bU0 = *(const uint4*)(bsrc + (size_t)(k0 + bkr) * HD);
            bU1 = *(const uint4*)(bsrc + (size_t)(k0 + bkr + 16) * HD);
        }
        warp_step(sAaddr + (uint32_t)buf * ABUF * 4u,
                  sBaddr + (uint32_t)buf * BBUF32 * 4u, m0, n0, lane, acc);
        if (more) {
            uint32_t* dA = sA + nbuf * ABUF;
            uint32_t* dB = sB + nbuf * BBUF32;
            *(uint4*)&dA[aPb]     = aV0;
            *(uint4*)&dA[aPb + 4] = aV1;
            *(uint4*)&dB[bIdx0] = bU0;
            *(uint4*)&dB[bIdx1] = bU1;
        }
        __syncthreads();
    }

    #pragma unroll
    for (int mt = 0; mt < 4; mt++) {
        int rA = m0 + mt * 16 + gid, rB = rA + 8;
        int tokA = stok[rA], tokB = stok[rB];
        float wA = sw[rA], wB = sw[rB];
        #pragma unroll
        for (int nt = 0; nt < 4; nt++) {
            int col = col0 + n0 + nt * 8 + tig * 2;
            float bb0 = b2[e * HD + col], bb1 = b2[e * HD + col + 1];
            if (tokA >= 0) {
                float* op = out + (size_t)tokA * HD + col;
                atomicAdd(op,     wA * (acc[mt][nt][0] + bb0));
                atomicAdd(op + 1, wA * (acc[mt][nt][1] + bb1));
            }
            if (tokB >= 0) {
                float* op = out + (size_t)tokB * HD + col;
                atomicAdd(op,     wB * (acc[mt][nt][2] + bb0));
                atomicAdd(op + 1, wB * (acc[mt][nt][3] + bb1));
            }
        }
    }
}

// ---------------- launch ----------------------------------------------------
extern "C" void kernel_launch(void* const* d_in, const int* in_sizes, int n_in,
                              void* d_out, int out_size)
{
    const float* X  = (const float*)d_in[0];
    const float* Wg = (const float*)d_in[1];
    const float* bg = (const float*)d_in[2];
    const float* W1 = (const float*)d_in[3];
    const float* b1 = (const float*)d_in[4];
    const float* W2 = (const float*)d_in[5];
    const float* b2 = (const float*)d_in[6];
    float* out = (float*)d_out;

    cudaMemsetAsync(out, 0, sizeof(float) * (size_t)NTOK * HD);

    {
        __half* w1h; cudaGetSymbolAddress((void**)&w1h, g_W1h);
        __half* w2h; cudaGetSymbolAddress((void**)&w2h, g_W2h);
        __half* xh;  cudaGetSymbolAddress((void**)&xh,  g_Xh);
        int nW = (int)((size_t)NE * HD * MD / 4);
        int nX = (int)((size_t)NTOK * HD / 4);
        f2h_kernel<<<(nW + 255) / 256, 256>>>(W1, w1h, nW);
        f2h_kernel<<<(nW + 255) / 256, 256>>>(W2, w2h, nW);
        f2h_kernel<<<(nX + 255) / 256, 256>>>(X,  xh,  nX);
    }

    init_kernel<<<(MAXSLOTS + 255) / 256, 256>>>();
    gate_kernel<<<(NTOK * 32 + 255) / 256, 256>>>(X, Wg, bg);
    scan_kernel<<<1, 1>>>();
    scatter_kernel<<<(NTOK + 255) / 256, 256>>>();

    fc1_kernel<<<dim3(MD / 128, ROWT), 256>>>(b1);
    fc2_kernel<<<dim3(HD / 128, ROWT), 256>>>(b2, out);
}